// round 3
// baseline (speedup 1.0000x reference)
#include <cuda_runtime.h>
#include <cuda_bf16.h>

// ROI bilinear pooling (tf.image.resize half-pixel-center semantics, per ROI).
// img:  (1, 64, 64, 1024) float32, NHWC
// rois: (1, R, 4) int32  [x, y, w, h]
// out:  (1, R, 7, 7, 1024) float32
//
// One CTA per output pixel (r, py, px); 256 threads x float4 = 1024 channels.
// R2: CTA-uniform duplicate-gather elision (clamped bilinear neighbors) +
//     packed f32x2 blend math.

#define POOL 7
#define HW   64
#define C    1024

typedef unsigned long long u64;

__device__ __forceinline__ u64 mul2(u64 a, u64 b) {
    u64 r; asm("mul.rn.f32x2 %0, %1, %2;" : "=l"(r) : "l"(a), "l"(b)); return r;
}
__device__ __forceinline__ u64 fma2(u64 a, u64 b, u64 c) {
    u64 r; asm("fma.rn.f32x2 %0, %1, %2, %3;" : "=l"(r) : "l"(a), "l"(b), "l"(c)); return r;
}
__device__ __forceinline__ u64 pack2(float v) {
    u64 r; asm("mov.b64 %0, {%1, %1};" : "=l"(r) : "r"(__float_as_uint(v))); return r;
}

union F4 {
    float4 v;
    u64 p[2];
};

__global__ __launch_bounds__(256) void roi_pool_kernel(
    const float* __restrict__ img,
    const int*   __restrict__ rois,
    float*       __restrict__ out)
{
    const int idx = blockIdx.x;          // r*49 + py*7 + px
    const int r  = idx / (POOL * POOL);
    const int p  = idx - r * (POOL * POOL);
    const int py = p / POOL;
    const int px = p - py * POOL;

    // ROI box (broadcast load)
    const int4 roi = __ldg(((const int4*)rois) + r);
    const int bx = roi.x, by = roi.y, bw = roi.z, bh = roi.w;

    // Vertical source coords (half-pixel centers, clamp-to-edge like reference)
    const float sy = (py + 0.5f) * ((float)bh / (float)POOL) - 0.5f;
    const float fy = floorf(sy);
    const float ty = sy - fy;
    const int   iy = (int)fy;
    const int   y0 = by + min(max(iy,     0), bh - 1);
    const int   y1 = by + min(max(iy + 1, 0), bh - 1);

    // Horizontal source coords
    const float sx = (px + 0.5f) * ((float)bw / (float)POOL) - 0.5f;
    const float fx = floorf(sx);
    const float tx = sx - fx;
    const int   ix = (int)fx;
    const int   x0 = bx + min(max(ix,     0), bw - 1);
    const int   x1 = bx + min(max(ix + 1, 0), bw - 1);

    const bool xdup = (x1 == x0);   // clamped neighbor -> b==a, d==g
    const bool ydup = (y1 == y0);   // clamped neighbor -> g==a, d==b

    const float4* p00 = (const float4*)(img + ((size_t)(y0 * HW + x0)) * C);
    const float4* p01 = (const float4*)(img + ((size_t)(y0 * HW + x1)) * C);
    const float4* p10 = (const float4*)(img + ((size_t)(y1 * HW + x0)) * C);
    const float4* p11 = (const float4*)(img + ((size_t)(y1 * HW + x1)) * C);

    const int c = threadIdx.x;           // 0..255, each handles one float4

    F4 a, b, g, d;
    a.v = __ldg(p00 + c);
    // CTA-uniform branches (roi/px/py identical across the block): no divergence.
    if (xdup) {
        if (ydup) {
            b = a; g = a; d = a;
        } else {
            g.v = __ldg(p10 + c);
            b = a; d = g;
        }
    } else if (ydup) {
        b.v = __ldg(p01 + c);
        g = a; d = b;
    } else {
        b.v = __ldg(p01 + c);
        g.v = __ldg(p10 + c);
        d.v = __ldg(p11 + c);
    }

    const u64 txp   = pack2(tx);
    const u64 wtx0p = pack2(1.0f - tx);
    const u64 typ   = pack2(ty);
    const u64 wty0p = pack2(1.0f - ty);

    F4 o;
#pragma unroll
    for (int i = 0; i < 2; i++) {
        u64 top = fma2(b.p[i], txp, mul2(a.p[i], wtx0p));
        u64 bot = fma2(d.p[i], txp, mul2(g.p[i], wtx0p));
        o.p[i]  = fma2(bot, typ, mul2(top, wty0p));
    }

    ((float4*)out)[(size_t)idx * (C / 4) + c] = o.v;
}

extern "C" void kernel_launch(void* const* d_in, const int* in_sizes, int n_in,
                              void* d_out, int out_size)
{
    const float* img  = (const float*)d_in[0];
    const int*   rois = (const int*)d_in[1];
    float*       out  = (float*)d_out;

    const int R = in_sizes[1] / 4;       // rois element count / 4 = number of ROIs
    const int blocks = R * POOL * POOL;  // one CTA per output pixel

    roi_pool_kernel<<<blocks, 256>>>(img, rois, out);
}

// round 5
// speedup vs baseline: 1.3322x; 1.3322x over previous
#include <cuda_runtime.h>
#include <cuda_bf16.h>

// ROI bilinear pooling (tf.image.resize half-pixel-center semantics, per ROI).
// img:  (1, 64, 64, 1024) float32, NHWC
// rois: (1, R, 4) int32  [x, y, w, h]
// out:  (1, R, 7, 7, 1024) float32
//
// R3: one CTA per output ROW (r, py). 256 threads, each owns one float4
// channel slice and iterates px=0..6. ROI decode + y-axis math + row base
// addresses amortized over 7 output pixels; unrolled loop exposes deep MLP.

#define POOL 7
#define HW   64
#define C    1024

__global__ __launch_bounds__(256) void roi_pool_row_kernel(
    const float* __restrict__ img,
    const int*   __restrict__ rois,
    float*       __restrict__ out)
{
    const int row = blockIdx.x;          // r*7 + py
    const int r   = row / POOL;
    const int py  = row - r * POOL;

    // ROI box (broadcast load)
    const int4 roi = __ldg(((const int4*)rois) + r);
    const int bx = roi.x, by = roi.y, bw = roi.z, bh = roi.w;

    // ---- vertical coords: once per CTA ----
    const float sy = (py + 0.5f) * ((float)bh / (float)POOL) - 0.5f;
    const float fy = floorf(sy);
    const float ty = sy - fy;
    const int   iy = (int)fy;
    const int   y0 = by + min(max(iy,     0), bh - 1);
    const int   y1 = by + min(max(iy + 1, 0), bh - 1);
    const float wty0 = 1.0f - ty;

    const float4* row0 = (const float4*)(img + (size_t)y0 * (HW * C));
    const float4* row1 = (const float4*)(img + (size_t)y1 * (HW * C));

    const int c = threadIdx.x;           // channel slice 0..255
    float4* outp = ((float4*)out) + (size_t)row * (POOL * (C / 4)) + c;

    const float xscale = (float)bw / (float)POOL;
    const int   xmax   = bw - 1;

#pragma unroll
    for (int px = 0; px < POOL; px++) {
        // ---- horizontal coords for this px ----
        const float sx = (px + 0.5f) * xscale - 0.5f;
        const float fx = floorf(sx);
        const float tx = sx - fx;
        const int   ix = (int)fx;
        const int   x0 = bx + min(max(ix,     0), xmax);
        const int   x1 = bx + min(max(ix + 1, 0), xmax);
        const float wtx0 = 1.0f - tx;

        const float4 a = __ldg(row0 + x0 * (C / 4) + c);
        const float4 b = __ldg(row0 + x1 * (C / 4) + c);
        const float4 g = __ldg(row1 + x0 * (C / 4) + c);
        const float4 d = __ldg(row1 + x1 * (C / 4) + c);

        float4 o;
        {
            float top = a.x * wtx0 + b.x * tx;
            float bot = g.x * wtx0 + d.x * tx;
            o.x = top * wty0 + bot * ty;
        }
        {
            float top = a.y * wtx0 + b.y * tx;
            float bot = g.y * wtx0 + d.y * tx;
            o.y = top * wty0 + bot * ty;
        }
        {
            float top = a.z * wtx0 + b.z * tx;
            float bot = g.z * wtx0 + d.z * tx;
            o.z = top * wty0 + bot * ty;
        }
        {
            float top = a.w * wtx0 + b.w * tx;
            float bot = g.w * wtx0 + d.w * tx;
            o.w = top * wty0 + bot * ty;
        }

        outp[px * (C / 4)] = o;
    }
}

extern "C" void kernel_launch(void* const* d_in, const int* in_sizes, int n_in,
                              void* d_out, int out_size)
{
    const float* img  = (const float*)d_in[0];
    const int*   rois = (const int*)d_in[1];
    float*       out  = (float*)d_out;

    const int R = in_sizes[1] / 4;       // number of ROIs
    const int blocks = R * POOL;         // one CTA per output row

    roi_pool_row_kernel<<<blocks, 256>>>(img, rois, out);
}